// round 7
// baseline (speedup 1.0000x reference)
#include <cuda_runtime.h>
#include <math.h>
#include <float.h>

// Divisive normalization over time — single streaming pass.
//   y1 recurrence (A,Bm), z2 = conv(y1,a2); max(y1) cancels in norm:
//   norm[t] = z2[t]/max z2.  drive[t] = y1[t]/max y1.
//   out = nan_to_num(|drive^n| / (|norm^n| + sigma)) at t_sel.
//
// R5 -> R6: the t-loop is now explicitly software-pipelined with prefetch
// distance PF=8 (register ring of float4). Each load's consumer is 8
// iterations later in program order, so every warp sustains ~8 outstanding
// LDG.128 (previously ~1 -> latency-bound at 37% DRAM).

#define PF 8

__global__ __launch_bounds__(64) void divnorm_kernel(
    const float* __restrict__ x,      // (T, P)
    const float* __restrict__ tau1,   // (CWH)
    const float* __restrict__ tau2,   // (CWH)
    const float* __restrict__ sigma,  // (CWH)
    const float* __restrict__ nexp,   // (CWH)
    const int*   __restrict__ t_sel,  // scalar
    float*       __restrict__ out,    // (P)
    int P4, int T, int CWH)
{
    int tid = blockIdx.x * blockDim.x + threadIdx.x;
    if (tid >= P4) return;
    const int p   = tid * 4;
    const int cwh = p % CWH;              // CWH % 4 == 0: group never crosses batch boundary
    const int tt  = *t_sel;

    const float4 t1 = *reinterpret_cast<const float4*>(tau1 + cwh);
    const float4 t2 = *reinterpret_cast<const float4*>(tau2 + cwh);

    float a1[4], a2[4];
    a1[0] = expf(-1.0f / t1.x); a1[1] = expf(-1.0f / t1.y);
    a1[2] = expf(-1.0f / t1.z); a1[3] = expf(-1.0f / t1.w);
    a2[0] = expf(-1.0f / t2.x); a2[1] = expf(-1.0f / t2.y);
    a2[2] = expf(-1.0f / t2.z); a2[3] = expf(-1.0f / t2.w);

    float A[4], Bm[4], c[4], my1[4], mz2[4], y1s[4], z2s[4];
#pragma unroll
    for (int i = 0; i < 4; ++i) {
        A[i] = 0.0f; Bm[i] = 0.0f; c[i] = 0.0f;
        my1[i] = -FLT_MAX; mz2[i] = -FLT_MAX;
        y1s[i] = 0.0f; z2s[i] = 0.0f;
    }

    const float4* __restrict__ x4 = reinterpret_cast<const float4*>(x) + tid;

    // ---- software pipeline: prime PF loads ----
    float4 buf[PF];
#pragma unroll
    for (int u = 0; u < PF; ++u) {
        if (u < T) buf[u] = __ldg(x4 + (size_t)u * P4);
    }

    for (int t0 = 0; t0 < T; t0 += PF) {
#pragma unroll
        for (int u = 0; u < PF; ++u) {
            const int t = t0 + u;
            if (t >= T) break;
            const float4 xv = buf[u];
            // issue the load for t+PF immediately; its consumer is PF steps away
            const int tl = t + PF;
            if (tl < T) buf[u] = __ldg(x4 + (size_t)tl * P4);

            const float xs[4] = {xv.x, xv.y, xv.z, xv.w};
            const bool sel = (t == tt);
#pragma unroll
            for (int i = 0; i < 4; ++i) {
                const float y1 = Bm[i];                  // scan output at t
                const float z2 = c[i];                   // scan output at t
                const float nA = fmaf(a1[i], A[i], xs[i]);
                const float nB = a1[i] * (Bm[i] + A[i]); // uses OLD A
                c[i]   = fmaf(a2[i], c[i], y1);          // z2 recurrence driven by y1[t]
                my1[i] = fmaxf(my1[i], y1);
                mz2[i] = fmaxf(mz2[i], z2);
                if (sel) { y1s[i] = y1; z2s[i] = z2; }
                A[i] = nA; Bm[i] = nB;
            }
        }
    }

    const float4 sg = *reinterpret_cast<const float4*>(sigma + cwh);
    const float4 nv = *reinterpret_cast<const float4*>(nexp + cwh);
    const float sgs[4] = {sg.x, sg.y, sg.z, sg.w};
    const float nvs[4] = {nv.x, nv.y, nv.z, nv.w};

    float4 ov;
    float* ovp = reinterpret_cast<float*>(&ov);
#pragma unroll
    for (int i = 0; i < 4; ++i) {
        const float drive = y1s[i] / my1[i];
        const float nrm   = z2s[i] / mz2[i];
        const float id    = fabsf(powf(drive, nvs[i]));
        const float nr    = fabsf(powf(nrm,  nvs[i])) + sgs[i];
        float r = id / nr;
        // nan_to_num semantics
        if (isnan(r))      r = 0.0f;
        else if (isinf(r)) r = (r > 0.0f) ? FLT_MAX : -FLT_MAX;
        ovp[i] = r;
    }
    *reinterpret_cast<float4*>(out + p) = ov;
}

extern "C" void kernel_launch(void* const* d_in, const int* in_sizes, int n_in,
                              void* d_out, int out_size)
{
    const float* x     = (const float*)d_in[0];
    const float* tau1  = (const float*)d_in[1];
    const float* tau2  = (const float*)d_in[2];
    const float* sigma = (const float*)d_in[3];
    const float* nexp  = (const float*)d_in[4];
    const int*   t_sel = (const int*)  d_in[5];
    float* out = (float*)d_out;

    const int P   = out_size;               // B*C*W*H = 262144
    const int T   = in_sizes[0] / P;        // 128
    const int CWH = in_sizes[3];            // 32768
    const int P4  = P / 4;

    const int threads = 64;                 // finer blocks -> even per-SM distribution
    const int blocks  = (P4 + threads - 1) / threads;
    divnorm_kernel<<<blocks, threads>>>(x, tau1, tau2, sigma, nexp, t_sel, out,
                                        P4, T, CWH);
}

// round 8
// speedup vs baseline: 2.4583x; 2.4583x over previous
#include <cuda_runtime.h>
#include <math.h>
#include <float.h>

// Divisive normalization over time — single streaming pass.
//   y1 recurrence (A,Bm); z2 = conv(y1,a2); max(y1) cancels in norm:
//   norm[t] = z2[t]/max z2.  drive[t] = y1[t]/max y1.
//   out = nan_to_num(|drive^n| / (|norm^n| + sigma)) at t_sel.
//
// R7 post-mortem: `break`/guards inside the unrolled pipeline body broke the
// unroll -> dynamic buf[] indexing -> 120 regs, serialized loads, 71us.
// R8: branch-free steady state. Prologue: PF unconditional loads. Main loop
// (t0 <= T-2*PF): consume buf[u], reload buf[u] via a marching pointer —
// all buf indices compile-time constants. Epilogue: PF predicated steps.

#define PF 8

__global__ __launch_bounds__(64) void divnorm_kernel(
    const float* __restrict__ x,      // (T, P)
    const float* __restrict__ tau1,   // (CWH)
    const float* __restrict__ tau2,   // (CWH)
    const float* __restrict__ sigma,  // (CWH)
    const float* __restrict__ nexp,   // (CWH)
    const int*   __restrict__ t_sel,  // scalar
    float*       __restrict__ out,    // (P)
    int P4, int T, int CWH)
{
    int tid = blockIdx.x * blockDim.x + threadIdx.x;
    if (tid >= P4) return;
    const int p   = tid * 4;
    const int cwh = p % CWH;              // CWH % 4 == 0: group never crosses batch boundary
    const int tt  = *t_sel;

    const float4 t1 = *reinterpret_cast<const float4*>(tau1 + cwh);
    const float4 t2 = *reinterpret_cast<const float4*>(tau2 + cwh);

    float a1[4], a2[4];
    a1[0] = expf(-1.0f / t1.x); a1[1] = expf(-1.0f / t1.y);
    a1[2] = expf(-1.0f / t1.z); a1[3] = expf(-1.0f / t1.w);
    a2[0] = expf(-1.0f / t2.x); a2[1] = expf(-1.0f / t2.y);
    a2[2] = expf(-1.0f / t2.z); a2[3] = expf(-1.0f / t2.w);

    float A[4], Bm[4], c[4], my1[4], mz2[4], y1s[4], z2s[4];
#pragma unroll
    for (int i = 0; i < 4; ++i) {
        A[i] = 0.0f; Bm[i] = 0.0f; c[i] = 0.0f;
        my1[i] = -FLT_MAX; mz2[i] = -FLT_MAX;
        y1s[i] = 0.0f; z2s[i] = 0.0f;
    }

    // One recurrence step at time t consuming xv. Branch-free except the
    // predicated t==tt select (compiles to FSEL/predicated moves).
    auto step = [&](int t, const float4& xv) {
        const float xs[4] = {xv.x, xv.y, xv.z, xv.w};
        const bool sel = (t == tt);
#pragma unroll
        for (int i = 0; i < 4; ++i) {
            const float y1 = Bm[i];                  // scan output at t
            const float z2 = c[i];                   // scan output at t
            const float nA = fmaf(a1[i], A[i], xs[i]);
            const float nB = a1[i] * (Bm[i] + A[i]); // uses OLD A
            c[i]   = fmaf(a2[i], c[i], y1);          // z2 recurrence driven by y1[t]
            my1[i] = fmaxf(my1[i], y1);
            mz2[i] = fmaxf(mz2[i], z2);
            y1s[i] = sel ? y1 : y1s[i];
            z2s[i] = sel ? z2 : z2s[i];
            A[i] = nA; Bm[i] = nB;
        }
    };

    const float4* __restrict__ x4 = reinterpret_cast<const float4*>(x) + tid;
    const float4* __restrict__ xp = x4;

    // ---- prologue: prime PF unconditional loads (T >= 2*PF assumed; T=128) ----
    float4 buf[PF];
#pragma unroll
    for (int u = 0; u < PF; ++u) {
        buf[u] = __ldg(xp);
        xp += P4;
    }

    // ---- steady state: branch-free, static buf indices, marching pointer ----
    int t0 = 0;
    for (; t0 + 2 * PF <= T; t0 += PF) {
#pragma unroll
        for (int u = 0; u < PF; ++u) {
            const float4 xv = buf[u];
            buf[u] = __ldg(xp);          // load for t0+u+PF; consumer is PF steps away
            xp += P4;
            step(t0 + u, xv);
        }
    }

    // ---- epilogue: last (T - t0) <= PF steps, predicated (no break) ----
#pragma unroll
    for (int u = 0; u < PF; ++u) {
        if (t0 + u < T) step(t0 + u, buf[u]);
    }

    const float4 sg = *reinterpret_cast<const float4*>(sigma + cwh);
    const float4 nv = *reinterpret_cast<const float4*>(nexp + cwh);
    const float sgs[4] = {sg.x, sg.y, sg.z, sg.w};
    const float nvs[4] = {nv.x, nv.y, nv.z, nv.w};

    float4 ov;
    float* ovp = reinterpret_cast<float*>(&ov);
#pragma unroll
    for (int i = 0; i < 4; ++i) {
        const float drive = y1s[i] / my1[i];
        const float nrm   = z2s[i] / mz2[i];
        const float id    = fabsf(powf(drive, nvs[i]));
        const float nr    = fabsf(powf(nrm,  nvs[i])) + sgs[i];
        float r = id / nr;
        // nan_to_num semantics
        if (isnan(r))      r = 0.0f;
        else if (isinf(r)) r = (r > 0.0f) ? FLT_MAX : -FLT_MAX;
        ovp[i] = r;
    }
    *reinterpret_cast<float4*>(out + p) = ov;
}

extern "C" void kernel_launch(void* const* d_in, const int* in_sizes, int n_in,
                              void* d_out, int out_size)
{
    const float* x     = (const float*)d_in[0];
    const float* tau1  = (const float*)d_in[1];
    const float* tau2  = (const float*)d_in[2];
    const float* sigma = (const float*)d_in[3];
    const float* nexp  = (const float*)d_in[4];
    const int*   t_sel = (const int*)  d_in[5];
    float* out = (float*)d_out;

    const int P   = out_size;               // B*C*W*H = 262144
    const int T   = in_sizes[0] / P;        // 128
    const int CWH = in_sizes[3];            // 32768
    const int P4  = P / 4;

    const int threads = 64;                 // fine blocks -> even per-SM distribution
    const int blocks  = (P4 + threads - 1) / threads;
    divnorm_kernel<<<blocks, threads>>>(x, tau1, tau2, sigma, nexp, t_sel, out,
                                        P4, T, CWH);
}